// round 5
// baseline (speedup 1.0000x reference)
#include <cuda_runtime.h>
#include <cuda_fp16.h>

#define OUT_DIM 11008
#define IN_DIM  4096
#define MTOK    2048

// ---------------- scratch (device globals; no runtime allocation) ----------------
__device__ __half g_Wh[(size_t)OUT_DIM * IN_DIM];
__device__ __half g_Xh[(size_t)MTOK * IN_DIM];

static __device__ __forceinline__ unsigned smem_u32(const void* p) {
    return (unsigned)__cvta_generic_to_shared(p);
}

#define CP16(dst_u32, src_ptr) \
    asm volatile("cp.async.cg.shared.global [%0], [%1], 16;" \
                 :: "r"(dst_u32), "l"(src_ptr) : "memory")

#define LDSM4(R, ADDR) \
    asm volatile("ldmatrix.sync.aligned.m8n8.x4.shared.b16 {%0,%1,%2,%3}, [%4];" \
                 : "=r"((R)[0]), "=r"((R)[1]), "=r"((R)[2]), "=r"((R)[3]) : "r"(ADDR))

#define MMA16816(C, A, B0, B1) \
    asm volatile("mma.sync.aligned.m16n8k16.row.col.f32.f16.f16.f32 " \
                 "{%0,%1,%2,%3}, {%4,%5,%6,%7}, {%8,%9}, {%0,%1,%2,%3};" \
                 : "+f"((C)[0]), "+f"((C)[1]), "+f"((C)[2]), "+f"((C)[3]) \
                 : "r"((A)[0]), "r"((A)[1]), "r"((A)[2]), "r"((A)[3]), \
                   "r"(B0), "r"(B1))

// ---------------- kernel 1: dequant packed int4 -> fp16 W ----------------
__global__ void dequant_kernel(const int* __restrict__ packed,
                               const float* __restrict__ scales) {
    size_t i = (size_t)blockIdx.x * blockDim.x + threadIdx.x;
    const size_t n = (size_t)OUT_DIM * (IN_DIM / 2);
    if (i >= n) return;
    int v = packed[i];
    int row = (int)(i >> 11);               // IN_DIM/2 = 2048
    float s = scales[row];
    float lo = (float)((v & 15) - 8) * s;         // original column 2j
    float hi = (float)(((v >> 4) & 15) - 8) * s;  // original column 2j+1
    reinterpret_cast<__half2*>(g_Wh)[i] = __floats2half2_rn(lo, hi);
}

// ---------------- kernel 2: sparse scatter-add (native fp16 atomics) ----------------
__global__ void scatter_kernel(const float* __restrict__ vals,
                               const int* __restrict__ rows,
                               const int* __restrict__ cols, int nnz) {
    int i = blockIdx.x * blockDim.x + threadIdx.x;
    if (i >= nnz) return;
    atomicAdd(&g_Wh[(size_t)rows[i] * IN_DIM + cols[i]], __float2half(vals[i]));
}

// ---------------- kernel 3: convert x -> fp16 ----------------
__global__ void convert_x_kernel(const float* __restrict__ x) {
    size_t i = (size_t)blockIdx.x * blockDim.x + threadIdx.x;
    const size_t n4 = (size_t)MTOK * IN_DIM / 4;
    if (i >= n4) return;
    float4 v = reinterpret_cast<const float4*>(x)[i];
    __half2* o = reinterpret_cast<__half2*>(g_Xh) + 2 * i;
    o[0] = __floats2half2_rn(v.x, v.y);
    o[1] = __floats2half2_rn(v.z, v.w);
}

// ---------------- kernel 4: mma.sync fp16 GEMM ----------------
// out = Xh * Wh^T, fp32 accumulate.
// CTA tile 128(M) x 256(N), 8 warps in 2x4 grid, warp tile 64x64, K-tile 32.
// 3-stage cp.async pipeline (stage = 8KB A + 16KB B = 24KB), 72KB dynamic smem.
// smem row layout (A rows 0..127, B rows 0..255): row r, 16B chunk c (0..3):
//   offset = r*64 + ((c ^ ((r>>1)&3)) << 4)   -- conflict-free STS.128 + LDSM
#define KTILE 32
#define A_BYTES 8192
#define B_BYTES 16384
#define STAGE_BYTES (A_BYTES + B_BYTES)
#define N_ITERS (IN_DIM / KTILE)   // 128

__global__ void __launch_bounds__(256, 1) gemm_kernel(float* __restrict__ out) {
    extern __shared__ char smem[];
    const int tid  = threadIdx.x;
    const int lane = tid & 31;
    const int w    = tid >> 5;
    const int wm   = w & 1;        // 0..1 : 64-row half (M)
    const int wn   = w >> 1;       // 0..3 : 64-col quarter (N)
    const int mt   = blockIdx.x;   // 0..15
    const int nt   = blockIdx.y;   // 0..42

    float c[4][8][4];
    #pragma unroll
    for (int mi = 0; mi < 4; ++mi)
        #pragma unroll
        for (int ni = 0; ni < 8; ++ni)
            #pragma unroll
            for (int q = 0; q < 4; ++q) c[mi][ni][q] = 0.f;

    // cp.async mapping: A 512 chunks (2/thread), B 1024 chunks (4/thread)
    const int lr  = tid >> 2;            // 0..63
    const int lc  = tid & 3;             // chunk 0..3
    #define SWZ(r_, c_) ((r_) * 64 + ((((c_) ^ (((r_) >> 1) & 3))) << 4))
    const int aO0 = SWZ(lr, lc);
    const int aO1 = SWZ(lr + 64, lc);
    const int bO0 = SWZ(lr, lc);
    const int bO1 = SWZ(lr + 64, lc);
    const int bO2 = SWZ(lr + 128, lc);
    const int bO3 = SWZ(lr + 192, lc);
    const unsigned sbase = smem_u32(smem);

    const __half* Ab = g_Xh + (size_t)mt * 128 * IN_DIM;
    const __half* Bb = g_Wh + (size_t)nt * 256 * IN_DIM;

    #define LOAD_TILE(it_) do {                                                   \
        int k0_ = (it_) << 5;                                                     \
        unsigned sa_ = sbase + ((it_) % 3) * STAGE_BYTES;                         \
        unsigned sb_ = sa_ + A_BYTES;                                             \
        const __half* ap_ = Ab + k0_ + lc * 8;                                    \
        const __half* bp_ = Bb + k0_ + lc * 8;                                    \
        CP16(sa_ + aO0, ap_ + (size_t)lr * IN_DIM);                               \
        CP16(sa_ + aO1, ap_ + (size_t)(lr + 64) * IN_DIM);                        \
        CP16(sb_ + bO0, bp_ + (size_t)lr * IN_DIM);                               \
        CP16(sb_ + bO1, bp_ + (size_t)(lr + 64) * IN_DIM);                        \
        CP16(sb_ + bO2, bp_ + (size_t)(lr + 128) * IN_DIM);                       \
        CP16(sb_ + bO3, bp_ + (size_t)(lr + 192) * IN_DIM);                       \
    } while (0)

    LOAD_TILE(0);
    asm volatile("cp.async.commit_group;" ::: "memory");
    LOAD_TILE(1);
    asm volatile("cp.async.commit_group;" ::: "memory");

    for (int it = 0; it < N_ITERS; ++it) {
        asm volatile("cp.async.wait_group 1;" ::: "memory");
        __syncthreads();

        unsigned sa = sbase + (it % 3) * STAGE_BYTES;
        unsigned sb = sa + A_BYTES;

        // ---- kk = 0 fragments ----
        unsigned a0[4][4], b0[4][4];
        #pragma unroll
        for (int mi = 0; mi < 4; ++mi) {
            int r = wm * 64 + mi * 16 + (lane & 15);
            int ci = (lane >> 4);
            LDSM4(a0[mi], sa + SWZ(r, ci));
        }
        #pragma unroll
        for (int nj = 0; nj < 4; ++nj) {
            int r = wn * 64 + nj * 16 + (lane & 7) + ((lane >> 4) << 3);
            int ci = ((lane >> 3) & 1);
            LDSM4(b0[nj], sb + SWZ(r, ci));
        }

        // prefetch stage (it+2)%3 while kk=0 math runs
        if (it + 2 < N_ITERS) LOAD_TILE(it + 2);
        asm volatile("cp.async.commit_group;" ::: "memory");

        #pragma unroll
        for (int mi = 0; mi < 4; ++mi)
            #pragma unroll
            for (int ni = 0; ni < 8; ++ni)
                MMA16816(c[mi][ni], a0[mi],
                         b0[ni >> 1][(ni & 1) * 2 + 0],
                         b0[ni >> 1][(ni & 1) * 2 + 1]);

        // ---- kk = 1 fragments ----
        unsigned a1[4][4], b1[4][4];
        #pragma unroll
        for (int mi = 0; mi < 4; ++mi) {
            int r = wm * 64 + mi * 16 + (lane & 15);
            int ci = 2 + (lane >> 4);
            LDSM4(a1[mi], sa + SWZ(r, ci));
        }
        #pragma unroll
        for (int nj = 0; nj < 4; ++nj) {
            int r = wn * 64 + nj * 16 + (lane & 7) + ((lane >> 4) << 3);
            int ci = 2 + ((lane >> 3) & 1);
            LDSM4(b1[nj], sb + SWZ(r, ci));
        }
        #pragma unroll
        for (int mi = 0; mi < 4; ++mi)
            #pragma unroll
            for (int ni = 0; ni < 8; ++ni)
                MMA16816(c[mi][ni], a1[mi],
                         b1[ni >> 1][(ni & 1) * 2 + 0],
                         b1[ni >> 1][(ni & 1) * 2 + 1]);
        // no trailing barrier: next iter's top barrier provides ordering
    }

    // ---- epilogue: direct fp32 stores ----
    const int r0 = mt * 128 + wm * 64 + (lane >> 2);
    const int c0 = nt * 256 + wn * 64 + (lane & 3) * 2;
    #pragma unroll
    for (int mi = 0; mi < 4; ++mi) {
        #pragma unroll
        for (int ni = 0; ni < 8; ++ni) {
            size_t rowA = (size_t)(r0 + mi * 16) * OUT_DIM + c0 + ni * 8;
            size_t rowB = rowA + (size_t)8 * OUT_DIM;
            float2 v01; v01.x = c[mi][ni][0]; v01.y = c[mi][ni][1];
            float2 v23; v23.x = c[mi][ni][2]; v23.y = c[mi][ni][3];
            *reinterpret_cast<float2*>(out + rowA) = v01;
            *reinterpret_cast<float2*>(out + rowB) = v23;
        }
    }
}

// ---------------- launcher ----------------
extern "C" void kernel_launch(void* const* d_in, const int* in_sizes, int n_in,
                              void* d_out, int out_size) {
    const float* x      = (const float*)d_in[0];
    const float* scales = (const float*)d_in[1];
    const float* vals   = (const float*)d_in[2];
    const int*   packed = (const int*)d_in[3];
    const int*   rows   = (const int*)d_in[4];
    const int*   cols   = (const int*)d_in[5];
    float* out = (float*)d_out;
    int nnz = in_sizes[2];

    // idempotent, non-stream API: safe under graph capture
    cudaFuncSetAttribute(gemm_kernel,
                         cudaFuncAttributeMaxDynamicSharedMemorySize,
                         3 * STAGE_BYTES);

    {
        size_t n = (size_t)OUT_DIM * (IN_DIM / 2);
        dequant_kernel<<<(unsigned)((n + 255) / 256), 256>>>(packed, scales);
    }
    scatter_kernel<<<(nnz + 255) / 256, 256>>>(vals, rows, cols, nnz);
    {
        size_t n4 = (size_t)MTOK * IN_DIM / 4;
        convert_x_kernel<<<(unsigned)((n4 + 255) / 256), 256>>>(x);
    }
    {
        dim3 grid(MTOK / 128, OUT_DIM / 256);  // (16, 43); x fastest -> B n-tile L2 reuse
        gemm_kernel<<<grid, 256, 3 * STAGE_BYTES>>>(out);
    }
}

// round 6
// speedup vs baseline: 1.0610x; 1.0610x over previous
#include <cuda_runtime.h>
#include <cuda_fp16.h>

#define OUT_DIM 11008
#define IN_DIM  4096
#define MTOK    2048

// ---------------- scratch (device globals; no runtime allocation) ----------------
__device__ __half g_Wh[(size_t)OUT_DIM * IN_DIM];
__device__ __half g_Xh[(size_t)MTOK * IN_DIM];

static __device__ __forceinline__ unsigned smem_u32(const void* p) {
    return (unsigned)__cvta_generic_to_shared(p);
}

#define CP16(dst_u32, src_ptr) \
    asm volatile("cp.async.cg.shared.global [%0], [%1], 16;" \
                 :: "r"(dst_u32), "l"(src_ptr) : "memory")

#define LDSM4(R, ADDR) \
    asm volatile("ldmatrix.sync.aligned.m8n8.x4.shared.b16 {%0,%1,%2,%3}, [%4];" \
                 : "=r"((R)[0]), "=r"((R)[1]), "=r"((R)[2]), "=r"((R)[3]) : "r"(ADDR))

#define MMA16816(C, A, B0, B1) \
    asm volatile("mma.sync.aligned.m16n8k16.row.col.f32.f16.f16.f32 " \
                 "{%0,%1,%2,%3}, {%4,%5,%6,%7}, {%8,%9}, {%0,%1,%2,%3};" \
                 : "+f"((C)[0]), "+f"((C)[1]), "+f"((C)[2]), "+f"((C)[3]) \
                 : "r"((A)[0]), "r"((A)[1]), "r"((A)[2]), "r"((A)[3]), \
                   "r"(B0), "r"(B1))

// ---------------- kernel 1: dequant packed int4 -> fp16 W ----------------
__global__ void dequant_kernel(const int* __restrict__ packed,
                               const float* __restrict__ scales) {
    size_t i = (size_t)blockIdx.x * blockDim.x + threadIdx.x;
    const size_t n = (size_t)OUT_DIM * (IN_DIM / 2);
    if (i >= n) return;
    int v = packed[i];
    int row = (int)(i >> 11);               // IN_DIM/2 = 2048
    float s = scales[row];
    float lo = (float)((v & 15) - 8) * s;         // original column 2j
    float hi = (float)(((v >> 4) & 15) - 8) * s;  // original column 2j+1
    reinterpret_cast<__half2*>(g_Wh)[i] = __floats2half2_rn(lo, hi);
}

// ---------------- kernel 2: sparse scatter-add (native fp16 atomics) ----------------
__global__ void scatter_kernel(const float* __restrict__ vals,
                               const int* __restrict__ rows,
                               const int* __restrict__ cols, int nnz) {
    int i = blockIdx.x * blockDim.x + threadIdx.x;
    if (i >= nnz) return;
    atomicAdd(&g_Wh[(size_t)rows[i] * IN_DIM + cols[i]], __float2half(vals[i]));
}

// ---------------- kernel 3: convert x -> fp16 ----------------
__global__ void convert_x_kernel(const float* __restrict__ x) {
    size_t i = (size_t)blockIdx.x * blockDim.x + threadIdx.x;
    const size_t n4 = (size_t)MTOK * IN_DIM / 4;
    if (i >= n4) return;
    float4 v = reinterpret_cast<const float4*>(x)[i];
    __half2* o = reinterpret_cast<__half2*>(g_Xh) + 2 * i;
    o[0] = __floats2half2_rn(v.x, v.y);
    o[1] = __floats2half2_rn(v.z, v.w);
}

// ---------------- kernel 4: mma.sync fp16 GEMM ----------------
// out = Xh * Wh^T, fp32 accumulate. CTA tile 128x128, 8 warps (2x4), warp tile
// 64x32, K-tile 64 (4 x k16 sub-steps), 3-stage cp.async pipeline (32KB/stage,
// 96KB total), 2 CTA/SM. ONE barrier + ONE wait_group per K-tile iteration.
// smem rows are 128B (64 halves): SWZ(r,c) = r*128 + ((c ^ (r&7))<<4), chunks
// c = 0..7 of 16B -- canonical SW128, conflict-free STS.128 + ldmatrix.
#define KTILE 64
#define A_BYTES 16384
#define STAGE_BYTES 32768
#define N_ITERS (IN_DIM / KTILE)   // 64

#define SWZ(r_, c_) ((r_) * 128 + ((((c_) ^ ((r_) & 7))) << 4))

__global__ void __launch_bounds__(256, 2) gemm_kernel(float* __restrict__ out) {
    extern __shared__ char smem[];
    const int tid  = threadIdx.x;
    const int lane = tid & 31;
    const int w    = tid >> 5;
    const int wm   = w & 1;        // 0..1 : 64-row half (M)
    const int wn   = w >> 1;       // 0..3 : 32-col quarter (N)
    const int mt   = blockIdx.x;   // 0..15
    const int nt   = blockIdx.y;   // 0..85

    float c[4][4][4];
    #pragma unroll
    for (int mi = 0; mi < 4; ++mi)
        #pragma unroll
        for (int ni = 0; ni < 4; ++ni)
            #pragma unroll
            for (int q = 0; q < 4; ++q) c[mi][ni][q] = 0.f;

    // cp.async mapping: 1024 16B-chunks per operand tile; 4 per thread each
    const int lr = tid >> 3;             // 0..31
    const int lc = tid & 7;              // chunk 0..7
    const unsigned sbase = smem_u32(smem);

    const __half* Ab = g_Xh + (size_t)mt * 128 * IN_DIM;
    const __half* Bb = g_Wh + (size_t)nt * 128 * IN_DIM;

    #define LOAD_TILE(it_) do {                                                   \
        int k0_ = (it_) << 6;                                                     \
        unsigned sa_ = sbase + ((it_) % 3) * STAGE_BYTES;                         \
        unsigned sb_ = sa_ + A_BYTES;                                             \
        const __half* ap_ = Ab + k0_ + lc * 8;                                    \
        const __half* bp_ = Bb + k0_ + lc * 8;                                    \
        _Pragma("unroll")                                                         \
        for (int p_ = 0; p_ < 4; ++p_) {                                          \
            int r_ = lr + p_ * 32;                                                \
            CP16(sa_ + SWZ(r_, lc), ap_ + (size_t)r_ * IN_DIM);                   \
            CP16(sb_ + SWZ(r_, lc), bp_ + (size_t)r_ * IN_DIM);                   \
        }                                                                         \
    } while (0)

    LOAD_TILE(0);
    asm volatile("cp.async.commit_group;" ::: "memory");
    LOAD_TILE(1);
    asm volatile("cp.async.commit_group;" ::: "memory");

    for (int it = 0; it < N_ITERS; ++it) {
        asm volatile("cp.async.wait_group 1;" ::: "memory");
        __syncthreads();

        unsigned sa = sbase + (it % 3) * STAGE_BYTES;
        unsigned sb = sa + A_BYTES;

        #pragma unroll
        for (int kk = 0; kk < 4; ++kk) {
            unsigned a[4][4], b[2][4];
            #pragma unroll
            for (int mi = 0; mi < 4; ++mi) {
                int r = wm * 64 + mi * 16 + (lane & 15);
                int ci = 2 * kk + (lane >> 4);
                LDSM4(a[mi], sa + SWZ(r, ci));
            }
            #pragma unroll
            for (int nj = 0; nj < 2; ++nj) {
                int r = wn * 32 + nj * 16 + (lane & 7) + ((lane >> 4) << 3);
                int ci = 2 * kk + ((lane >> 3) & 1);
                LDSM4(b[nj], sb + SWZ(r, ci));
            }

            if (kk == 0) {   // prefetch stage (it+2)%3 while kk=0 math runs
                if (it + 2 < N_ITERS) LOAD_TILE(it + 2);
                asm volatile("cp.async.commit_group;" ::: "memory");
            }

            #pragma unroll
            for (int mi = 0; mi < 4; ++mi)
                #pragma unroll
                for (int ni = 0; ni < 4; ++ni)
                    MMA16816(c[mi][ni], a[mi],
                             b[ni >> 1][(ni & 1) * 2 + 0],
                             b[ni >> 1][(ni & 1) * 2 + 1]);
        }
        // no trailing barrier: next iter's top barrier provides ordering
    }

    // ---- epilogue: direct fp32 stores ----
    const int r0 = mt * 128 + wm * 64 + (lane >> 2);
    const int c0 = nt * 128 + wn * 32 + (lane & 3) * 2;
    #pragma unroll
    for (int mi = 0; mi < 4; ++mi) {
        #pragma unroll
        for (int ni = 0; ni < 4; ++ni) {
            size_t rowA = (size_t)(r0 + mi * 16) * OUT_DIM + c0 + ni * 8;
            size_t rowB = rowA + (size_t)8 * OUT_DIM;
            float2 v01; v01.x = c[mi][ni][0]; v01.y = c[mi][ni][1];
            float2 v23; v23.x = c[mi][ni][2]; v23.y = c[mi][ni][3];
            *reinterpret_cast<float2*>(out + rowA) = v01;
            *reinterpret_cast<float2*>(out + rowB) = v23;
        }
    }
}

// ---------------- launcher ----------------
extern "C" void kernel_launch(void* const* d_in, const int* in_sizes, int n_in,
                              void* d_out, int out_size) {
    const float* x      = (const float*)d_in[0];
    const float* scales = (const float*)d_in[1];
    const float* vals   = (const float*)d_in[2];
    const int*   packed = (const int*)d_in[3];
    const int*   rows   = (const int*)d_in[4];
    const int*   cols   = (const int*)d_in[5];
    float* out = (float*)d_out;
    int nnz = in_sizes[2];

    // idempotent, non-stream API: safe under graph capture
    cudaFuncSetAttribute(gemm_kernel,
                         cudaFuncAttributeMaxDynamicSharedMemorySize,
                         3 * STAGE_BYTES);

    {
        size_t n = (size_t)OUT_DIM * (IN_DIM / 2);
        dequant_kernel<<<(unsigned)((n + 255) / 256), 256>>>(packed, scales);
    }
    scatter_kernel<<<(nnz + 255) / 256, 256>>>(vals, rows, cols, nnz);
    {
        size_t n4 = (size_t)MTOK * IN_DIM / 4;
        convert_x_kernel<<<(unsigned)((n4 + 255) / 256), 256>>>(x);
    }
    {
        dim3 grid(MTOK / 128, OUT_DIM / 128);  // (16, 86); x fastest -> B n-tile L2 reuse
        gemm_kernel<<<grid, 256, 3 * STAGE_BYTES>>>(out);
    }
}